// round 11
// baseline (speedup 1.0000x reference)
#include <cuda_runtime.h>
#include <cuda_bf16.h>
#include <cstdint>
#include <math.h>

// Problem constants (B=4, L=2048, H=8, E=64)
#define BB 4
#define LL 2048
#define HH 8
#define EE 64
#define NBH (BB*HH)           // 32
#define NROWS (NBH*LL)        // 65536
#define SCALEF 0.125f
#define STRIDE_L (HH*EE)      // 512

// Scratch (device globals)
__device__ float g_sigv[NROWS];
__device__ float g_coef[NROWS];
__device__ float g_inv2s2[NROWS];

// ---- smem layout (bytes). bf16 tiles: 128x64 = 16384 B each, SW128 ----
// Total 97.25 KB -> two CTAs co-resident per SM.
#define OFF_INV   0            // 128 f32 rowsum reciprocals
#define OFF_QHI   1024
#define OFF_QLO   17408
#define OFF_KHI   33792
#define OFF_KLO   50176
#define OFF_VHI   66560
#define OFF_VLO   82944
#define SMEM_BYTES 99328

__device__ __forceinline__ uint32_t swz(uint32_t x) { return x ^ ((x >> 3) & 0x70); }

__device__ __forceinline__ uint32_t smem_u32(const void* p) {
    uint32_t a;
    asm("{ .reg .u64 t; cvta.to.shared.u64 t, %1; cvt.u32.u64 %0, t; }"
        : "=r"(a) : "l"(p));
    return a;
}
__device__ __forceinline__ void ldsm4(uint32_t r[4], uint32_t addr) {
    asm volatile("ldmatrix.sync.aligned.m8n8.x4.shared.b16 {%0,%1,%2,%3}, [%4];"
                 : "=r"(r[0]), "=r"(r[1]), "=r"(r[2]), "=r"(r[3]) : "r"(addr));
}
__device__ __forceinline__ void ldsm4t(uint32_t r[4], uint32_t addr) {
    asm volatile("ldmatrix.sync.aligned.m8n8.x4.trans.shared.b16 {%0,%1,%2,%3}, [%4];"
                 : "=r"(r[0]), "=r"(r[1]), "=r"(r[2]), "=r"(r[3]) : "r"(addr));
}
__device__ __forceinline__ void mma_bf16(float d[4], const uint32_t a[4],
                                         uint32_t b0, uint32_t b1) {
    asm volatile(
        "mma.sync.aligned.m16n8k16.row.col.f32.bf16.bf16.f32 "
        "{%0,%1,%2,%3}, {%4,%5,%6,%7}, {%8,%9}, {%0,%1,%2,%3};"
        : "+f"(d[0]), "+f"(d[1]), "+f"(d[2]), "+f"(d[3])
        : "r"(a[0]), "r"(a[1]), "r"(a[2]), "r"(a[3]), "r"(b0), "r"(b1));
}
__device__ __forceinline__ uint32_t packbf(float a, float b) {   // a -> low half
    __nv_bfloat162 t = __float22bfloat162_rn(make_float2(a, b));
    return *reinterpret_cast<uint32_t*>(&t);
}
__device__ __forceinline__ uint32_t packresid(float a, float b, uint32_t hi) {
    __nv_bfloat162 t = *reinterpret_cast<__nv_bfloat162*>(&hi);
    return packbf(a - __bfloat162float(t.x), b - __bfloat162float(t.y));
}

// ---------------------------------------------------------------------------
// K0: per-row sigma transform (verified R1-R9)
// ---------------------------------------------------------------------------
__global__ void k_sig(const float* __restrict__ sigma) {
    int i = blockIdx.x * 256 + threadIdx.x;
    if (i >= NROWS) return;
    int bh = i >> 11;
    int l  = i & 2047;
    int b = bh >> 3, h = bh & 7;
    float x = sigma[((size_t)b * LL + l) * HH + h];
    float s32 = (float)(1.0 / (1.0 + exp(-5.0 * (double)x)));
    float sg  = s32 + 1e-5f;
    float p   = (float)exp((double)sg * 1.0986122886681098);
    float s   = p - 1.0f;
    g_sigv[i]   = s;
    g_coef[i]   = 1.0f / (2.5066282746310002f * s);
    g_inv2s2[i] = 1.0f / (2.0f * s * s);
}

// ---------------------------------------------------------------------------
// Fused flash kernel: 256 threads / 8 warps, 128 Q-rows per CTA, 2 CTAs/SM.
// jp-interleaved GEMM1->exp->GEMM2 (<=128 regs). Warp w owns rows
// [w*16, w*16+16). Diagonal-tile jp chunks beyond the warp's rows store
// zeros without MMA/exp.
// ---------------------------------------------------------------------------
__global__ void __launch_bounds__(256, 2)
k_fused(const float* __restrict__ Q, const float* __restrict__ K,
        const float* __restrict__ V, float* __restrict__ series,
        float* __restrict__ out) {
    extern __shared__ __align__(1024) char smem[];
    float* smf = (float*)smem;
    uint32_t sb = smem_u32(smem);
    int tid = threadIdx.x, wid = tid >> 5, lane = tid & 31;
    int bh = blockIdx.x, b = bh >> 3, h = bh & 7;
    int ti = 15 - blockIdx.y, l0 = ti * 128;   // bh-major grid: all ti=15 first
    int R0 = wid * 16;
    int g = lane >> 2, tig = lane & 3;
    int L8 = lane & 7, m = lane >> 3;

    const float* Qb = Q + (size_t)b * LL * STRIDE_L + h * EE;
    const float* Kb = K + (size_t)b * LL * STRIDE_L + h * EE;
    const float* Vb = V + (size_t)b * LL * STRIDE_L + h * EE;
    float* Srow = series + ((size_t)bh * LL + l0) * LL;

    int e4 = tid & 15, r0 = tid >> 4;   // 16 thr/row mapping for tile loads

    // ---- Q tile -> smem bf16 hi/lo, [l][e], SW128 rows of 128B ----
    {
#pragma unroll
        for (int ps = 0; ps < 8; ps++) {
            int row = r0 + ps * 16;
            float4 v = *(const float4*)&Qb[(size_t)(l0 + row) * STRIDE_L + e4 * 4];
            uint32_t h0 = packbf(v.x, v.y), h1 = packbf(v.z, v.w);
            uint32_t sw = swz(row * 128 + e4 * 8);
            *(uint2*)(smem + OFF_QHI + sw) = make_uint2(h0, h1);
            *(uint2*)(smem + OFF_QLO + sw) =
                make_uint2(packresid(v.x, v.y, h0), packresid(v.z, v.w, h1));
        }
    }
    __syncthreads();

    // ---- Preload Q fragments (4 k-steps, hi+lo) ----
    uint32_t qh[4][4], ql[4][4];
    {
        uint32_t ro = (uint32_t)(R0 + (m & 1) * 8 + L8) * 128 + (m >> 1) * 16;
#pragma unroll
        for (int ks = 0; ks < 4; ks++) {
            uint32_t sw = swz(ro + ks * 32);
            ldsm4(qh[ks], sb + OFF_QHI + sw);
            ldsm4(ql[ks], sb + OFF_QLO + sw);
        }
    }

    float oacc[8][4];
#pragma unroll
    for (int t = 0; t < 8; t++)
#pragma unroll
        for (int c = 0; c < 4; c++) oacc[t][c] = 0.f;
    float rs0 = 0.f, rs1 = 0.f;
    int gl0 = l0 + R0 + g, gl1 = gl0 + 8;

    uint32_t k_ro = (uint32_t)((m >> 1) * 8 + L8) * 128 + (m & 1) * 16;   // K (no trans)
    uint32_t v_ro = (uint32_t)((m & 1) * 8 + L8) * 128 + (m >> 1) * 16;   // V (trans)

    for (int tj = 0; tj <= ti; tj++) {
        int j0 = tj * 128;
        __syncthreads();   // previous tile's smem reads complete

        // ---- K/V tiles: gmem -> bf16 hi/lo smem (other CTA hides latency) ----
        {
#pragma unroll
            for (int ps = 0; ps < 8; ps++) {
                int row = r0 + ps * 16;
                float4 v = *(const float4*)&Kb[(size_t)(j0 + row) * STRIDE_L + e4 * 4];
                uint32_t h0 = packbf(v.x, v.y), h1 = packbf(v.z, v.w);
                uint32_t sw = swz(row * 128 + e4 * 8);
                *(uint2*)(smem + OFF_KHI + sw) = make_uint2(h0, h1);
                *(uint2*)(smem + OFF_KLO + sw) =
                    make_uint2(packresid(v.x, v.y, h0), packresid(v.z, v.w, h1));
                float4 w = *(const float4*)&Vb[(size_t)(j0 + row) * STRIDE_L + e4 * 4];
                uint32_t g0 = packbf(w.x, w.y), g1 = packbf(w.z, w.w);
                *(uint2*)(smem + OFF_VHI + sw) = make_uint2(g0, g1);
                *(uint2*)(smem + OFF_VLO + sw) =
                    make_uint2(packresid(w.x, w.y, g0), packresid(w.z, w.w, g1));
            }
        }
        __syncthreads();

        bool diag = (tj == ti);

        // ---- Interleaved per jp (16 S-cols): GEMM1 -> exp -> GEMM2 ----
#pragma unroll
        for (int jp = 0; jp < 8; jp++) {
            // Diagonal tile: columns beyond this warp's rows are fully masked.
            // Store zeros (k_prior doesn't cover intra-diagonal-tile zeros),
            // skip all MMA/exp work.
            if (diag && jp > wid) {
                int gja = j0 + (2 * jp) * 8 + tig * 2;
                int gjb = j0 + (2 * jp + 1) * 8 + tig * 2;
                float2 z = make_float2(0.f, 0.f);
                *(float2*)&Srow[(size_t)(R0 + g) * LL + gja]     = z;
                *(float2*)&Srow[(size_t)(R0 + 8 + g) * LL + gja] = z;
                *(float2*)&Srow[(size_t)(R0 + g) * LL + gjb]     = z;
                *(float2*)&Srow[(size_t)(R0 + 8 + g) * LL + gjb] = z;
                continue;
            }
            float s0[4] = {0.f, 0.f, 0.f, 0.f};
            float s1[4] = {0.f, 0.f, 0.f, 0.f};
#pragma unroll
            for (int ks = 0; ks < 4; ks++) {
                uint32_t sw = swz(k_ro + (uint32_t)jp * 16 * 128 + ks * 32);
                uint32_t bh_[4], bl_[4];
                ldsm4(bh_, sb + OFF_KHI + sw);
                ldsm4(bl_, sb + OFF_KLO + sw);
                mma_bf16(s0, qh[ks], bh_[0], bh_[1]);
                mma_bf16(s0, qh[ks], bl_[0], bl_[1]);
                mma_bf16(s0, ql[ks], bh_[0], bh_[1]);
                mma_bf16(s1, qh[ks], bh_[2], bh_[3]);
                mma_bf16(s1, qh[ks], bl_[2], bl_[3]);
                mma_bf16(s1, ql[ks], bh_[2], bh_[3]);
            }
            // exp + mask + rowsum + series store (unnormalized)
            {
                int gj = j0 + (2 * jp) * 8 + tig * 2;
                float e0 = __expf(SCALEF * s0[0]);
                float e1 = __expf(SCALEF * s0[1]);
                float e2 = __expf(SCALEF * s0[2]);
                float e3 = __expf(SCALEF * s0[3]);
                e0 = (gj     <= gl0) ? e0 : 0.f;
                e1 = (gj + 1 <= gl0) ? e1 : 0.f;
                e2 = (gj     <= gl1) ? e2 : 0.f;
                e3 = (gj + 1 <= gl1) ? e3 : 0.f;
                rs0 += e0 + e1; rs1 += e2 + e3;
                s0[0] = e0; s0[1] = e1; s0[2] = e2; s0[3] = e3;
                *(float2*)&Srow[(size_t)(R0 + g) * LL + gj]     = make_float2(e0, e1);
                *(float2*)&Srow[(size_t)(R0 + 8 + g) * LL + gj] = make_float2(e2, e3);
            }
            {
                int gj = j0 + (2 * jp + 1) * 8 + tig * 2;
                float e0 = __expf(SCALEF * s1[0]);
                float e1 = __expf(SCALEF * s1[1]);
                float e2 = __expf(SCALEF * s1[2]);
                float e3 = __expf(SCALEF * s1[3]);
                e0 = (gj     <= gl0) ? e0 : 0.f;
                e1 = (gj + 1 <= gl0) ? e1 : 0.f;
                e2 = (gj     <= gl1) ? e2 : 0.f;
                e3 = (gj + 1 <= gl1) ? e3 : 0.f;
                rs0 += e0 + e1; rs1 += e2 + e3;
                s1[0] = e0; s1[1] = e1; s1[2] = e2; s1[3] = e3;
                *(float2*)&Srow[(size_t)(R0 + g) * LL + gj]     = make_float2(e0, e1);
                *(float2*)&Srow[(size_t)(R0 + 8 + g) * LL + gj] = make_float2(e2, e3);
            }
            // GEMM2 k-step kk = jp
            {
                uint32_t ah[4], al[4];
                ah[0] = packbf(s0[0], s0[1]); ah[1] = packbf(s0[2], s0[3]);
                ah[2] = packbf(s1[0], s1[1]); ah[3] = packbf(s1[2], s1[3]);
                al[0] = packresid(s0[0], s0[1], ah[0]);
                al[1] = packresid(s0[2], s0[3], ah[1]);
                al[2] = packresid(s1[0], s1[1], ah[2]);
                al[3] = packresid(s1[2], s1[3], ah[3]);
#pragma unroll
                for (int ep = 0; ep < 4; ep++) {
                    uint32_t sw = swz(v_ro + (uint32_t)jp * 16 * 128 + ep * 32);
                    uint32_t vh_[4], vl_[4];
                    ldsm4t(vh_, sb + OFF_VHI + sw);
                    ldsm4t(vl_, sb + OFF_VLO + sw);
                    mma_bf16(oacc[2 * ep],     ah, vh_[0], vh_[1]);
                    mma_bf16(oacc[2 * ep],     ah, vl_[0], vl_[1]);
                    mma_bf16(oacc[2 * ep],     al, vh_[0], vh_[1]);
                    mma_bf16(oacc[2 * ep + 1], ah, vh_[2], vh_[3]);
                    mma_bf16(oacc[2 * ep + 1], ah, vl_[2], vl_[3]);
                    mma_bf16(oacc[2 * ep + 1], al, vh_[2], vh_[3]);
                }
            }
        }
    }

    // ---- row sums: reduce over the 4 tig lanes ----
    rs0 += __shfl_xor_sync(0xFFFFFFFF, rs0, 1);
    rs0 += __shfl_xor_sync(0xFFFFFFFF, rs0, 2);
    rs1 += __shfl_xor_sync(0xFFFFFFFF, rs1, 1);
    rs1 += __shfl_xor_sync(0xFFFFFFFF, rs1, 2);
    float inv0 = 1.0f / rs0, inv1 = 1.0f / rs1;
    if (tig == 0) {
        smf[OFF_INV / 4 + R0 + g]     = inv0;
        smf[OFF_INV / 4 + R0 + 8 + g] = inv1;
    }

    // ---- O epilogue (own rows) ----
#pragma unroll
    for (int t = 0; t < 8; t++) {
        int col = t * 8 + tig * 2;
        float* d0 = out + (((size_t)b * LL + gl0) * HH + h) * EE + col;
        float* d1 = out + (((size_t)b * LL + gl1) * HH + h) * EE + col;
        *(float2*)d0 = make_float2(oacc[t][0] * inv0, oacc[t][1] * inv0);
        *(float2*)d1 = make_float2(oacc[t][2] * inv1, oacc[t][3] * inv1);
    }
    __syncthreads();

    // ---- in-place series renormalization (rows of this CTA's block) ----
    {
        int ncols4 = (l0 + 128) >> 2;
#pragma unroll 1
        for (int rr = wid; rr < 128; rr += 8) {
            float inv = smf[OFF_INV / 4 + rr];
            float* rowp = series + ((size_t)bh * LL + l0 + rr) * LL;
#pragma unroll 1
            for (int c4 = lane; c4 < ncols4; c4 += 32) {
                float4 s = *(float4*)&rowp[c4 * 4];
                s.x *= inv; s.y *= inv; s.z *= inv; s.w *= inv;
                *(float4*)&rowp[c4 * 4] = s;
            }
        }
    }
}

// ---------------------------------------------------------------------------
// k_prior: prior + sig everywhere; zero series in strictly-upper 128-tiles.
// ---------------------------------------------------------------------------
__global__ void __launch_bounds__(256) k_prior(float* __restrict__ prior,
                                               float* __restrict__ sig,
                                               float* __restrict__ series) {
    int bh = blockIdx.z;
    int ti = blockIdx.y, tj = blockIdx.x;
    int l0 = ti * 128, j0 = tj * 128;
    bool upper = (tj > ti);
    int tid = threadIdx.x;
    int c4 = (tid & 31) * 4;
    int r0 = tid >> 5;
#pragma unroll 4
    for (int it = 0; it < 16; it++) {
        int lr = r0 + it * 8;
        int gl = l0 + lr;
        size_t rowi = (size_t)bh * LL + gl;
        float coef = g_coef[rowi];
        float i2s  = g_inv2s2[rowi];
        float sv   = g_sigv[rowi];
        float p[4];
#pragma unroll
        for (int c = 0; c < 4; c++) {
            int gj = j0 + c4 + c;
            int d  = gl - gj;
            float d2 = (float)(d * d);
            p[c] = coef * __expf(-d2 * i2s);
        }
        size_t idx = rowi * LL + j0 + c4;
        *(float4*)&prior[idx] = make_float4(p[0], p[1], p[2], p[3]);
        *(float4*)&sig[idx]   = make_float4(sv, sv, sv, sv);
        if (upper)
            *(float4*)&series[idx] = make_float4(0.f, 0.f, 0.f, 0.f);
    }
}

// ---------------------------------------------------------------------------
extern "C" void kernel_launch(void* const* d_in, const int* in_sizes, int n_in,
                              void* d_out, int out_size) {
    const float* Q = (const float*)d_in[0];
    const float* K = (const float*)d_in[1];
    const float* V = (const float*)d_in[2];
    const float* S = (const float*)d_in[3];
    float* out = (float*)d_out;

    float* outV      = out;
    float* outSeries = outV + (size_t)BB * LL * HH * EE;
    float* outPrior  = outSeries + (size_t)NBH * LL * LL;
    float* outSig    = outPrior + (size_t)NBH * LL * LL;

    cudaFuncSetAttribute(k_fused, cudaFuncAttributeMaxDynamicSharedMemorySize,
                         SMEM_BYTES);

    k_sig<<<NROWS / 256, 256>>>(S);
    // bh-major grid: all heavy (ti=15) CTAs dispatch first -> LPT wave balance
    k_fused<<<dim3(NBH, 16), 256, SMEM_BYTES>>>(Q, K, V, outSeries, outV);
    k_prior<<<dim3(16, 16, NBH), 256>>>(outPrior, outSig, outSeries);
}

// round 12
// speedup vs baseline: 1.0392x; 1.0392x over previous
#include <cuda_runtime.h>
#include <cuda_bf16.h>
#include <cstdint>
#include <math.h>

// Problem constants (B=4, L=2048, H=8, E=64)
#define BB 4
#define LL 2048
#define HH 8
#define EE 64
#define NBH (BB*HH)           // 32
#define NROWS (NBH*LL)        // 65536
#define SCALEF 0.125f
#define STRIDE_L (HH*EE)      // 512

// Scratch (device globals)
__device__ float g_sigv[NROWS];
__device__ float g_coef[NROWS];
__device__ float g_inv2s2[NROWS];

// ---- smem layout (bytes). bf16 tiles: 128x64 = 16384 B each, SW128 ----
#define OFF_INV   0            // 128 f32 rowsum reciprocals
#define OFF_QHI   1024
#define OFF_QLO   17408
#define OFF_KHI   33792
#define OFF_KLO   50176
#define OFF_VHI   66560
#define OFF_VLO   82944
#define OFF_SK    99328        // f32 staging K: 128 rows x 256 B
#define OFF_SV    132096       // f32 staging V: 128 rows x 256 B
#define SMEM_BYTES 164864

__device__ __forceinline__ uint32_t swz(uint32_t x) { return x ^ ((x >> 3) & 0x70); }

__device__ __forceinline__ uint32_t smem_u32(const void* p) {
    uint32_t a;
    asm("{ .reg .u64 t; cvta.to.shared.u64 t, %1; cvt.u32.u64 %0, t; }"
        : "=r"(a) : "l"(p));
    return a;
}
__device__ __forceinline__ void ldsm4(uint32_t r[4], uint32_t addr) {
    asm volatile("ldmatrix.sync.aligned.m8n8.x4.shared.b16 {%0,%1,%2,%3}, [%4];"
                 : "=r"(r[0]), "=r"(r[1]), "=r"(r[2]), "=r"(r[3]) : "r"(addr));
}
__device__ __forceinline__ void ldsm4t(uint32_t r[4], uint32_t addr) {
    asm volatile("ldmatrix.sync.aligned.m8n8.x4.trans.shared.b16 {%0,%1,%2,%3}, [%4];"
                 : "=r"(r[0]), "=r"(r[1]), "=r"(r[2]), "=r"(r[3]) : "r"(addr));
}
__device__ __forceinline__ void mma_bf16(float d[4], const uint32_t a[4],
                                         uint32_t b0, uint32_t b1) {
    asm volatile(
        "mma.sync.aligned.m16n8k16.row.col.f32.bf16.bf16.f32 "
        "{%0,%1,%2,%3}, {%4,%5,%6,%7}, {%8,%9}, {%0,%1,%2,%3};"
        : "+f"(d[0]), "+f"(d[1]), "+f"(d[2]), "+f"(d[3])
        : "r"(a[0]), "r"(a[1]), "r"(a[2]), "r"(a[3]), "r"(b0), "r"(b1));
}
__device__ __forceinline__ uint32_t packbf(float a, float b) {   // a -> low half
    __nv_bfloat162 t = __float22bfloat162_rn(make_float2(a, b));
    return *reinterpret_cast<uint32_t*>(&t);
}
__device__ __forceinline__ uint32_t packresid(float a, float b, uint32_t hi) {
    __nv_bfloat162 t = *reinterpret_cast<__nv_bfloat162*>(&hi);
    return packbf(a - __bfloat162float(t.x), b - __bfloat162float(t.y));
}
__device__ __forceinline__ void cpasync16(uint32_t dst, const void* src) {
    asm volatile("cp.async.cg.shared.global [%0], [%1], 16;"
                 :: "r"(dst), "l"(src) : "memory");
}
#define CP_COMMIT() asm volatile("cp.async.commit_group;" ::: "memory")
#define CP_WAIT0()  asm volatile("cp.async.wait_group 0;" ::: "memory")

// ---------------------------------------------------------------------------
// K0: per-row sigma transform (verified R1-R10)
// ---------------------------------------------------------------------------
__global__ void k_sig(const float* __restrict__ sigma) {
    int i = blockIdx.x * 256 + threadIdx.x;
    if (i >= NROWS) return;
    int bh = i >> 11;
    int l  = i & 2047;
    int b = bh >> 3, h = bh & 7;
    float x = sigma[((size_t)b * LL + l) * HH + h];
    float s32 = (float)(1.0 / (1.0 + exp(-5.0 * (double)x)));
    float sg  = s32 + 1e-5f;
    float p   = (float)exp((double)sg * 1.0986122886681098);
    float s   = p - 1.0f;
    g_sigv[i]   = s;
    g_coef[i]   = 1.0f / (2.5066282746310002f * s);
    g_inv2s2[i] = 1.0f / (2.0f * s * s);
}

// ---------------------------------------------------------------------------
// Fused flash kernel — byte-identical to R8's best-measured version.
// 256 threads, 8 warps; warp w owns output rows [w*16, w*16+16).
// Whole-tile sacc, cp.async K/V staging.
// ---------------------------------------------------------------------------
__global__ void __launch_bounds__(256, 1)
k_fused(const float* __restrict__ Q, const float* __restrict__ K,
        const float* __restrict__ V, float* __restrict__ series,
        float* __restrict__ out) {
    extern __shared__ __align__(1024) char smem[];
    float* smf = (float*)smem;
    uint32_t sb = smem_u32(smem);
    int tid = threadIdx.x, wid = tid >> 5, lane = tid & 31;
    int bh = blockIdx.y, b = bh >> 3, h = bh & 7;
    int ti = 15 - blockIdx.x, l0 = ti * 128;
    int R0 = wid * 16;
    int g = lane >> 2, tig = lane & 3;
    int L8 = lane & 7, m = lane >> 3;

    const float* Qb = Q + (size_t)b * LL * STRIDE_L + h * EE;
    const float* Kb = K + (size_t)b * LL * STRIDE_L + h * EE;
    const float* Vb = V + (size_t)b * LL * STRIDE_L + h * EE;
    float* Srow = series + ((size_t)bh * LL + l0) * LL;

    int e4 = tid & 15, r0 = tid >> 4;   // shared thread mapping for loads

    // ---- prefetch tile 0 K/V into f32 staging ----
    {
#pragma unroll
        for (int ps = 0; ps < 8; ps++) {
            int row = r0 + ps * 16;
            cpasync16(sb + OFF_SK + row * 256 + e4 * 16,
                      Kb + (size_t)row * STRIDE_L + e4 * 4);
            cpasync16(sb + OFF_SV + row * 256 + e4 * 16,
                      Vb + (size_t)row * STRIDE_L + e4 * 4);
        }
        CP_COMMIT();
    }

    // ---- Q tile -> smem bf16 hi/lo, [l][e], SW128 rows of 128B ----
    {
#pragma unroll
        for (int ps = 0; ps < 8; ps++) {
            int row = r0 + ps * 16;
            float4 v = *(const float4*)&Qb[(size_t)(l0 + row) * STRIDE_L + e4 * 4];
            uint32_t h0 = packbf(v.x, v.y), h1 = packbf(v.z, v.w);
            uint32_t sw = swz(row * 128 + e4 * 8);
            *(uint2*)(smem + OFF_QHI + sw) = make_uint2(h0, h1);
            *(uint2*)(smem + OFF_QLO + sw) =
                make_uint2(packresid(v.x, v.y, h0), packresid(v.z, v.w, h1));
        }
    }
    __syncthreads();

    // ---- Preload Q fragments (4 k-steps, hi+lo) ----
    uint32_t qh[4][4], ql[4][4];
    {
        uint32_t ro = (uint32_t)(R0 + (m & 1) * 8 + L8) * 128 + (m >> 1) * 16;
#pragma unroll
        for (int ks = 0; ks < 4; ks++) {
            uint32_t sw = swz(ro + ks * 32);
            ldsm4(qh[ks], sb + OFF_QHI + sw);
            ldsm4(ql[ks], sb + OFF_QLO + sw);
        }
    }

    float oacc[8][4];
#pragma unroll
    for (int t = 0; t < 8; t++)
#pragma unroll
        for (int c = 0; c < 4; c++) oacc[t][c] = 0.f;
    float rs0 = 0.f, rs1 = 0.f;
    int gl0 = l0 + R0 + g, gl1 = gl0 + 8;

    // lane-offsets for B-fragment ldmatrix addresses
    uint32_t k_ro = (uint32_t)((m >> 1) * 8 + L8) * 128 + (m & 1) * 16;   // K (no trans)
    uint32_t v_ro = (uint32_t)((m & 1) * 8 + L8) * 128 + (m >> 1) * 16;   // V (trans)

    for (int tj = 0; tj <= ti; tj++) {
        int j0 = tj * 128;
        CP_WAIT0();
        __syncthreads();   // staging visible to all; previous tile's smem reads done

        // ---- convert staged f32 -> bf16 hi/lo smem tiles (K and V) ----
        {
#pragma unroll
            for (int ps = 0; ps < 8; ps++) {
                int row = r0 + ps * 16;
                float4 v = *(const float4*)(smem + OFF_SK + row * 256 + e4 * 16);
                uint32_t h0 = packbf(v.x, v.y), h1 = packbf(v.z, v.w);
                uint32_t sw = swz(row * 128 + e4 * 8);
                *(uint2*)(smem + OFF_KHI + sw) = make_uint2(h0, h1);
                *(uint2*)(smem + OFF_KLO + sw) =
                    make_uint2(packresid(v.x, v.y, h0), packresid(v.z, v.w, h1));
                float4 w = *(const float4*)(smem + OFF_SV + row * 256 + e4 * 16);
                uint32_t g0 = packbf(w.x, w.y), g1 = packbf(w.z, w.w);
                *(uint2*)(smem + OFF_VHI + sw) = make_uint2(g0, g1);
                *(uint2*)(smem + OFF_VLO + sw) =
                    make_uint2(packresid(w.x, w.y, g0), packresid(w.z, w.w, g1));
            }
        }
        __syncthreads();   // converts visible; staging free for reuse

        // ---- prefetch tile tj+1 (overlaps entire MMA phase below) ----
        if (tj < ti) {
            int jn = j0 + 128;
#pragma unroll
            for (int ps = 0; ps < 8; ps++) {
                int row = r0 + ps * 16;
                cpasync16(sb + OFF_SK + row * 256 + e4 * 16,
                          Kb + (size_t)(jn + row) * STRIDE_L + e4 * 4);
                cpasync16(sb + OFF_SV + row * 256 + e4 * 16,
                          Vb + (size_t)(jn + row) * STRIDE_L + e4 * 4);
            }
            CP_COMMIT();
        }

        // ---- GEMM1: S = Q.K^T via 3-term bf16 split ----
        float sacc[16][4];
#pragma unroll
        for (int t = 0; t < 16; t++)
#pragma unroll
            for (int c = 0; c < 4; c++) sacc[t][c] = 0.f;

#pragma unroll
        for (int jp = 0; jp < 8; jp++) {
#pragma unroll
            for (int ks = 0; ks < 4; ks++) {
                uint32_t sw = swz(k_ro + (uint32_t)jp * 16 * 128 + ks * 32);
                uint32_t bh_[4], bl_[4];
                ldsm4(bh_, sb + OFF_KHI + sw);
                ldsm4(bl_, sb + OFF_KLO + sw);
                mma_bf16(sacc[2 * jp],     qh[ks], bh_[0], bh_[1]);
                mma_bf16(sacc[2 * jp],     qh[ks], bl_[0], bl_[1]);
                mma_bf16(sacc[2 * jp],     ql[ks], bh_[0], bh_[1]);
                mma_bf16(sacc[2 * jp + 1], qh[ks], bh_[2], bh_[3]);
                mma_bf16(sacc[2 * jp + 1], qh[ks], bl_[2], bl_[3]);
                mma_bf16(sacc[2 * jp + 1], ql[ks], bh_[2], bh_[3]);
            }
        }

        // ---- softmax numerator + series store (unnormalized) ----
#pragma unroll
        for (int t = 0; t < 16; t++) {
            int gj = j0 + t * 8 + tig * 2;
            float e0 = __expf(SCALEF * sacc[t][0]);
            float e1 = __expf(SCALEF * sacc[t][1]);
            float e2 = __expf(SCALEF * sacc[t][2]);
            float e3 = __expf(SCALEF * sacc[t][3]);
            e0 = (gj     <= gl0) ? e0 : 0.f;
            e1 = (gj + 1 <= gl0) ? e1 : 0.f;
            e2 = (gj     <= gl1) ? e2 : 0.f;
            e3 = (gj + 1 <= gl1) ? e3 : 0.f;
            rs0 += e0 + e1;
            rs1 += e2 + e3;
            sacc[t][0] = e0; sacc[t][1] = e1; sacc[t][2] = e2; sacc[t][3] = e3;
            *(float2*)&Srow[(size_t)(R0 + g) * LL + gj]     = make_float2(e0, e1);
            *(float2*)&Srow[(size_t)(R0 + 8 + g) * LL + gj] = make_float2(e2, e3);
        }

        // ---- GEMM2: O += P.V, P fragments straight from registers ----
#pragma unroll
        for (int kk = 0; kk < 8; kk++) {
            const float* x = sacc[2 * kk];
            const float* y = sacc[2 * kk + 1];
            uint32_t ah[4], al[4];
            ah[0] = packbf(x[0], x[1]); ah[1] = packbf(x[2], x[3]);
            ah[2] = packbf(y[0], y[1]); ah[3] = packbf(y[2], y[3]);
            al[0] = packresid(x[0], x[1], ah[0]);
            al[1] = packresid(x[2], x[3], ah[1]);
            al[2] = packresid(y[0], y[1], ah[2]);
            al[3] = packresid(y[2], y[3], ah[3]);
#pragma unroll
            for (int ep = 0; ep < 4; ep++) {
                uint32_t sw = swz(v_ro + (uint32_t)kk * 16 * 128 + ep * 32);
                uint32_t vh_[4], vl_[4];
                ldsm4t(vh_, sb + OFF_VHI + sw);
                ldsm4t(vl_, sb + OFF_VLO + sw);
                mma_bf16(oacc[2 * ep],     ah, vh_[0], vh_[1]);
                mma_bf16(oacc[2 * ep],     ah, vl_[0], vl_[1]);
                mma_bf16(oacc[2 * ep],     al, vh_[0], vh_[1]);
                mma_bf16(oacc[2 * ep + 1], ah, vh_[2], vh_[3]);
                mma_bf16(oacc[2 * ep + 1], ah, vl_[2], vl_[3]);
                mma_bf16(oacc[2 * ep + 1], al, vh_[2], vh_[3]);
            }
        }
    }

    // ---- row sums: reduce over the 4 tig lanes ----
    rs0 += __shfl_xor_sync(0xFFFFFFFF, rs0, 1);
    rs0 += __shfl_xor_sync(0xFFFFFFFF, rs0, 2);
    rs1 += __shfl_xor_sync(0xFFFFFFFF, rs1, 1);
    rs1 += __shfl_xor_sync(0xFFFFFFFF, rs1, 2);
    float inv0 = 1.0f / rs0, inv1 = 1.0f / rs1;
    if (tig == 0) {
        smf[OFF_INV / 4 + R0 + g]     = inv0;
        smf[OFF_INV / 4 + R0 + 8 + g] = inv1;
    }

    // ---- O epilogue (own rows; no cross-warp data needed) ----
#pragma unroll
    for (int t = 0; t < 8; t++) {
        int col = t * 8 + tig * 2;
        float* d0 = out + (((size_t)b * LL + gl0) * HH + h) * EE + col;
        float* d1 = out + (((size_t)b * LL + gl1) * HH + h) * EE + col;
        *(float2*)d0 = make_float2(oacc[t][0] * inv0, oacc[t][1] * inv0);
        *(float2*)d1 = make_float2(oacc[t][2] * inv1, oacc[t][3] * inv1);
    }
    __syncthreads();

    // ---- in-place series renormalization (rows of this CTA's block) ----
    {
        int ncols4 = (l0 + 128) >> 2;
        for (int rr = wid; rr < 128; rr += 8) {
            float inv = smf[OFF_INV / 4 + rr];
            float* rowp = series + ((size_t)bh * LL + l0 + rr) * LL;
            for (int c4 = lane; c4 < ncols4; c4 += 32) {
                float4 s = *(float4*)&rowp[c4 * 4];
                s.x *= inv; s.y *= inv; s.z *= inv; s.w *= inv;
                *(float4*)&rowp[c4 * 4] = s;
            }
        }
    }
}

// ---------------------------------------------------------------------------
// k_prior: prior + sig everywhere; zero series in strictly-upper tiles.
// Writes are disjoint from k_fused's -> safe to run concurrently with it.
// ---------------------------------------------------------------------------
__global__ void __launch_bounds__(256) k_prior(float* __restrict__ prior,
                                               float* __restrict__ sig,
                                               float* __restrict__ series) {
    int bh = blockIdx.z;
    int ti = blockIdx.y, tj = blockIdx.x;
    int l0 = ti * 128, j0 = tj * 128;
    bool upper = (tj > ti);
    int tid = threadIdx.x;
    int c4 = (tid & 31) * 4;
    int r0 = tid >> 5;
#pragma unroll 4
    for (int it = 0; it < 16; it++) {
        int lr = r0 + it * 8;
        int gl = l0 + lr;
        size_t rowi = (size_t)bh * LL + gl;
        float coef = g_coef[rowi];
        float i2s  = g_inv2s2[rowi];
        float sv   = g_sigv[rowi];
        float p[4];
#pragma unroll
        for (int c = 0; c < 4; c++) {
            int gj = j0 + c4 + c;
            int d  = gl - gj;
            float d2 = (float)(d * d);
            p[c] = coef * __expf(-d2 * i2s);
        }
        size_t idx = rowi * LL + j0 + c4;
        *(float4*)&prior[idx] = make_float4(p[0], p[1], p[2], p[3]);
        *(float4*)&sig[idx]   = make_float4(sv, sv, sv, sv);
        if (upper)
            *(float4*)&series[idx] = make_float4(0.f, 0.f, 0.f, 0.f);
    }
}

// ---------------------------------------------------------------------------
// Launcher: k_sig, then FORK -> {k_fused on main stream, k_prior on side
// stream} -> JOIN. The two kernels touch disjoint memory; running them
// concurrently overlaps k_prior's DRAM-bound phase with k_fused's
// compute-bound phase. Streams/events are created per call and intentionally
// not destroyed (destroying a forked stream during an active capture would
// invalidate the capture; these are host-side objects, no device memory).
// ---------------------------------------------------------------------------
extern "C" void kernel_launch(void* const* d_in, const int* in_sizes, int n_in,
                              void* d_out, int out_size) {
    const float* Q = (const float*)d_in[0];
    const float* K = (const float*)d_in[1];
    const float* V = (const float*)d_in[2];
    const float* S = (const float*)d_in[3];
    float* out = (float*)d_out;

    float* outV      = out;
    float* outSeries = outV + (size_t)BB * LL * HH * EE;
    float* outPrior  = outSeries + (size_t)NBH * LL * LL;
    float* outSig    = outPrior + (size_t)NBH * LL * LL;

    cudaFuncSetAttribute(k_fused, cudaFuncAttributeMaxDynamicSharedMemorySize,
                         SMEM_BYTES);

    cudaStream_t side;
    cudaStreamCreateWithFlags(&side, cudaStreamNonBlocking);
    cudaEvent_t eFork, eJoin;
    cudaEventCreateWithFlags(&eFork, cudaEventDisableTiming);
    cudaEventCreateWithFlags(&eJoin, cudaEventDisableTiming);

    k_sig<<<NROWS / 256, 256>>>(S);

    // fork: side stream depends on k_sig
    cudaEventRecord(eFork, 0);
    cudaStreamWaitEvent(side, eFork, 0);

    // concurrent pair
    k_prior<<<dim3(16, 16, NBH), 256, 0, side>>>(outPrior, outSig, outSeries);
    cudaEventRecord(eJoin, side);
    k_fused<<<dim3(16, NBH), 256, SMEM_BYTES>>>(Q, K, V, outSeries, outV);

    // join: main stream waits for k_prior before harness reads d_out
    cudaStreamWaitEvent(0, eJoin, 0);
}